// round 13
// baseline (speedup 1.0000x reference)
#include <cuda_runtime.h>

#define NCTA   128
#define TPB    512
#define PP     1024
#define DD     32
#define RS     1032
#define MAXIT  30
#define EPSV   0.1f
#define LN2F   0.69314718055994530942f
#define ALPHA  14.4269504088896340736f   /* 1/(eps*ln2) */
#define THRESH 0.1f

typedef unsigned long long u64;

__device__ unsigned          g_cnt = 0;
__device__ volatile unsigned g_gen = 0;
__device__ float2 g_pm[NCTA * PP];                 // iter-0 (max,sum) partials
__device__ float  g_csum[(MAXIT + 1) * 4 * PP];    // per-iter per-batch col sums (atomic)
__device__ float  g_errb[(MAXIT + 1) * 4 * 8];     // per-iter per-batch err (padded)
__device__ float  g_b2[4 * PP];                    // B after iter 0
__device__ double g_costp[NCTA];

struct Smem {
    float  K2[32 * RS];        // 132096 B
    float  bb[PP];             // current B (local)
    float  lnu2[PP];
    float  ystage[256 * DD];   // 32 KB setup staging
    double redd[TPB];
    float  A2s[32];
    float  lmu2s[32];
    float  rowShift[32];
    float  errw[16];
    float  err4[4];
    float  Sx, Sy;
};

__device__ __forceinline__ float ex2f(float x){ float r; asm("ex2.approx.ftz.f32 %0, %1;" : "=f"(r) : "f"(x)); return r; }
__device__ __forceinline__ float lg2f(float x){ float r; asm("lg2.approx.f32 %0, %1;" : "=f"(r) : "f"(x)); return r; }
__device__ __forceinline__ u64 pk2(float lo, float hi){ u64 r; asm("mov.b64 %0, {%1, %2};" : "=l"(r) : "f"(lo), "f"(hi)); return r; }
__device__ __forceinline__ void upk2(u64 v, float& lo, float& hi){ asm("mov.b64 {%0, %1}, %2;" : "=f"(lo), "=f"(hi) : "l"(v)); }
__device__ __forceinline__ void fma2(u64& d, u64 a, u64 b){ asm("fma.rn.f32x2 %0, %1, %2, %0;" : "+l"(d) : "l"(a), "l"(b)); }
__device__ __forceinline__ u64 add2(u64 a, u64 b){ u64 r; asm("add.rn.f32x2 %0, %1, %2;" : "=l"(r) : "l"(a), "l"(b)); return r; }

// R3-style global barrier: single atomic counter + single generation flag.
__device__ __forceinline__ void gbar(unsigned target) {
    __syncthreads();
    if (threadIdx.x == 0) {
        __threadfence();
        if (atomicAdd(&g_cnt, 1u) == NCTA - 1u) {
            g_cnt = 0;
            __threadfence();
            g_gen = target;
        } else {
            while (g_gen != target) { }
            __threadfence();
        }
    }
    __syncthreads();
}

__global__ void __launch_bounds__(TPB, 1)
sinkhorn_kernel(const float* __restrict__ gx, const float* __restrict__ gy,
                const float* __restrict__ gxw, const float* __restrict__ gyw,
                float* __restrict__ gout)
{
    extern __shared__ __align__(16) char smraw[];
    Smem* S = reinterpret_cast<Smem*>(smraw);

    const int tid  = threadIdx.x;
    const int lane = tid & 31;
    const int warp = tid >> 5;       // 0..15
    const int bid  = blockIdx.x;
    const int nb   = bid >> 5;
    const int sub  = bid & 31;
    const int r0   = sub * 32;

    unsigned tgt = g_gen;    // quiescent base; read before any release

    // ---- zero per-launch atomic accumulators (disjoint slices) ----
    for (int k = bid * TPB + tid; k < (MAXIT + 1) * 4 * PP; k += NCTA * TPB)
        g_csum[k] = 0.f;
    if (bid == 0)
        for (int k = tid; k < (MAXIT + 1) * 4 * 8; k += TPB) g_errb[k] = 0.f;

    // ---- global weight sums (redundant per CTA, deterministic) ----
    {
        float px = 0.f, py = 0.f;
        for (int k = tid; k < 4096; k += TPB) { px += gxw[k]; py += gyw[k]; }
        S->redd[tid] = (double)px; __syncthreads();
        for (int s = TPB/2; s > 0; s >>= 1) { if (tid < s) S->redd[tid] += S->redd[tid+s]; __syncthreads(); }
        if (tid == 0) S->Sx = (float)S->redd[0];
        __syncthreads();
        S->redd[tid] = (double)py; __syncthreads();
        for (int s = TPB/2; s > 0; s >>= 1) { if (tid < s) S->redd[tid] += S->redd[tid+s]; __syncthreads(); }
        if (tid == 0) S->Sy = (float)S->redd[0];
        __syncthreads();
    }

    if (tid < 32) {
        S->lmu2s[tid] = lg2f(gxw[nb * PP + r0 + tid] / S->Sx + 1e-8f);
        S->A2s[tid]   = 0.f;
    }
    for (int c = tid; c < PP; c += TPB)
        S->lnu2[c] = lg2f(gyw[nb * PP + c] / S->Sy + 1e-8f);

    // ---- build K2 = -C/(eps*ln2) in SMEM ----
    const float* ybase = gy + (size_t)nb * PP * DD;
    for (int c = tid; c < PP; c += TPB) {
        const float4* yc = (const float4*)(ybase + c * DD);
        float s = 0.f;
#pragma unroll
        for (int q = 0; q < 8; q++) { float4 v = yc[q]; s += v.x*v.x + v.y*v.y + v.z*v.z + v.w*v.w; }
        S->bb[c] = s * ALPHA;   // temp: ALPHA*|y|^2
    }
    float xv[32];
    {
        const float4* xr = (const float4*)(gx + (size_t)(nb * PP + r0 + lane) * DD);
#pragma unroll
        for (int q = 0; q < 8; q++) {
            float4 v = xr[q];
            xv[4*q] = v.x; xv[4*q+1] = v.y; xv[4*q+2] = v.z; xv[4*q+3] = v.w;
        }
    }
    float x2 = 0.f;
#pragma unroll
    for (int d = 0; d < 32; d++) x2 += xv[d] * xv[d];
    const float cx = ALPHA * x2;
    u64 xp[16];
#pragma unroll
    for (int q = 0; q < 16; q++) xp[q] = pk2(xv[2*q], xv[2*q+1]);
    __syncthreads();

    for (int chunk = 0; chunk < 4; chunk++) {
        const int j0 = chunk * 256;
        const float4* ysrc = (const float4*)(ybase + j0 * DD);
        float4* yst = (float4*)S->ystage;
#pragma unroll
        for (int q = 0; q < 4; q++) yst[tid + TPB * q] = ysrc[tid + TPB * q];
        __syncthreads();
#pragma unroll 4
        for (int m = 0; m < 16; m++) {
            const int jj = warp + 16 * m;
            const ulonglong2* yp = (const ulonglong2*)(S->ystage + jj * DD);
            u64 acc[4] = {0ull, 0ull, 0ull, 0ull};
#pragma unroll
            for (int q = 0; q < 8; q++) {
                ulonglong2 w = yp[q];
                fma2(acc[(2*q)   & 3], xp[2*q],     w.x);
                fma2(acc[(2*q+1) & 3], xp[2*q + 1], w.y);
            }
            u64 st = add2(add2(acc[0], acc[1]), add2(acc[2], acc[3]));
            float lo, hi; upk2(st, lo, hi);
            float dot = lo + hi;
            S->K2[lane * RS + j0 + jj] = fmaf(dot, 2.f * ALPHA, -(cx + S->bb[j0 + jj]));
        }
        __syncthreads();
    }

    // row maxes (iter-0 shift; exact since B=0 at iter 0): warp handles rows 2w, 2w+1
#pragma unroll
    for (int k = 0; k < 2; k++) {
        const int r = warp * 2 + k;
        const float4* kr = (const float4*)(S->K2 + r * RS);
        float m = -1e30f;
#pragma unroll
        for (int q = 0; q < 8; q++) {
            float4 a = kr[lane + 32 * q];
            m = fmaxf(m, fmaxf(fmaxf(a.x, a.y), fmaxf(a.z, a.w)));
        }
#pragma unroll
        for (int o = 16; o; o >>= 1) m = fmaxf(m, __shfl_xor_sync(0xffffffffu, m, o));
        if (lane == 0) S->rowShift[r] = m;
    }
#pragma unroll
    for (int cc = 0; cc < 2; cc++) S->bb[tid + TPB * cc] = 0.f;

    gbar(++tgt);   // accumulator zeroing visible before any atomicAdd

    const int c0 = 2 * tid, c1 = 2 * tid + 1;   // owned columns (512 threads x 2)

    // ================= Sinkhorn iterations =================
    int iter = 0;
    for (;;) {
        // ---------- row (u) update: warp handles rows 2w, 2w+1; shift = prev LSE ----------
        {
            const float4* b4 = (const float4*)S->bb;
            const float4* kr0 = (const float4*)(S->K2 + (warp * 2 + 0) * RS);
            const float4* kr1 = (const float4*)(S->K2 + (warp * 2 + 1) * RS);
            const float m0 = S->rowShift[warp * 2 + 0];
            const float m1 = S->rowShift[warp * 2 + 1];
            float s0 = 0.f, s1 = 0.f;
#pragma unroll
            for (int q = 0; q < 8; q++) {
                const int ix = lane + 32 * q;
                float4 b = b4[ix];
                float4 a0 = kr0[ix], a1 = kr1[ix];
                s0 += ex2f(a0.x + b.x - m0) + ex2f(a0.y + b.y - m0)
                    + ex2f(a0.z + b.z - m0) + ex2f(a0.w + b.w - m0);
                s1 += ex2f(a1.x + b.x - m1) + ex2f(a1.y + b.y - m1)
                    + ex2f(a1.z + b.z - m1) + ex2f(a1.w + b.w - m1);
            }
#pragma unroll
            for (int o = 16; o; o >>= 1) {
                s0 += __shfl_xor_sync(0xffffffffu, s0, o);
                s1 += __shfl_xor_sync(0xffffffffu, s1, o);
            }
            if (lane == 0) {
                float lse0 = m0 + lg2f(s0), lse1 = m1 + lg2f(s1);
                const int r = warp * 2;
                float a0 = S->lmu2s[r+0] - lse0, a1 = S->lmu2s[r+1] - lse1;
                S->errw[warp] = fabsf(a0 - S->A2s[r+0]) + fabsf(a1 - S->A2s[r+1]);
                S->A2s[r+0] = a0; S->A2s[r+1] = a1;
                S->rowShift[r+0] = lse0; S->rowShift[r+1] = lse1;
            }
        }
        __syncthreads();
        if (tid == 0) {
            float e = 0.f;
#pragma unroll
            for (int w = 0; w < 16; w++) e += S->errw[w];
            atomicAdd(&g_errb[(iter * 4 + nb) * 8], e);
        }

        // ---------- column reduction (2 cols/thread) ----------
        if (iter == 0) {
            float m0 = -1e30f, m1 = -1e30f;
#pragma unroll
            for (int r = 0; r < 32; r++) {
                const float ar = S->A2s[r];
                float2 ka = *(const float2*)(S->K2 + r * RS + c0);
                m0 = fmaxf(m0, ka.x + ar);
                m1 = fmaxf(m1, ka.y + ar);
            }
            float s0 = 0.f, s1 = 0.f;
#pragma unroll
            for (int r = 0; r < 32; r++) {
                const float ar = S->A2s[r];
                float2 ka = *(const float2*)(S->K2 + r * RS + c0);
                s0 += ex2f(ka.x + (ar - m0));
                s1 += ex2f(ka.y + (ar - m1));
            }
            *(float4*)(g_pm + (size_t)bid * PP + c0) = make_float4(m0, s0, m1, s1);
            gbar(++tgt);

            // warp-shuffle combine: warp w handles cols sub*32 + {2w, 2w+1}; lane = CTA partial
#pragma unroll
            for (int cc = 0; cc < 2; cc++) {
                const int gcol = sub * 32 + warp * 2 + cc;
                float2 p = __ldcg(&g_pm[(size_t)(nb * 32 + lane) * PP + gcol]);
                float M = p.x, Ss = p.y;
#pragma unroll
                for (int o = 16; o; o >>= 1) {
                    float M2 = __shfl_xor_sync(0xffffffffu, M, o);
                    float S2 = __shfl_xor_sync(0xffffffffu, Ss, o);
                    float Mn = fmaxf(M, M2);
                    Ss = Ss * ex2f(M - Mn) + S2 * ex2f(M2 - Mn);
                    M = Mn;
                }
                if (lane == 0)
                    __stcg(&g_b2[nb * PP + gcol],
                           S->lnu2[gcol] - (M + lg2f(Ss)));
            }
            gbar(++tgt);
            if (tid < 256)
                ((float4*)S->bb)[tid] = __ldcg(((const float4*)(g_b2 + nb * PP)) + tid);
        } else {
            const float mc0 = S->lnu2[c0] - S->bb[c0];
            const float mc1 = S->lnu2[c1] - S->bb[c1];
            float s0 = 0.f, s1 = 0.f;
#pragma unroll
            for (int r = 0; r < 32; r++) {
                const float ar = S->A2s[r];
                float2 ka = *(const float2*)(S->K2 + r * RS + c0);
                s0 += ex2f(ka.x + (ar - mc0));
                s1 += ex2f(ka.y + (ar - mc1));
            }
            float* cs = g_csum + (size_t)(iter * 4 + nb) * PP;
            atomicAdd(cs + c0, s0);
            atomicAdd(cs + c1, s1);
            gbar(++tgt);

            // local B update: B_new = B_old - log2(colsum)
            float2 sv = __ldcg((const float2*)(g_csum + (size_t)(iter * 4 + nb) * PP + c0));
            float2 bo = *(float2*)(S->bb + c0);
            bo.x -= lg2f(sv.x);
            bo.y -= lg2f(sv.y);
            *(float2*)(S->bb + c0) = bo;
        }

        // ---------- err gather + decide ----------
        if (tid < 4) S->err4[tid] = __ldcg(&g_errb[(iter * 4 + tid) * 8]);
        __syncthreads();
        float ev = (S->err4[0] + S->err4[1]) + (S->err4[2] + S->err4[3]);

        iter++;
        if (iter >= MAXIT) break;
        if (ev * (EPSV * LN2F * 0.25f) < THRESH) break;
    }

    // ---- final cost: cost_n = -eps*ln2 * sum 2^(K2+A+B) * K2 ----
    {
        const float bc0 = S->bb[c0], bc1 = S->bb[c1];
        float acc = 0.f;
#pragma unroll 8
        for (int r = 0; r < 32; r++) {
            const float ar = S->A2s[r];
            float2 ka = *(const float2*)(S->K2 + r * RS + c0);
            acc = fmaf(ex2f(ka.x + ar + bc0), ka.x, acc);
            acc = fmaf(ex2f(ka.y + ar + bc1), ka.y, acc);
        }
        S->redd[tid] = (double)acc; __syncthreads();
        for (int s = TPB/2; s > 0; s >>= 1) { if (tid < s) S->redd[tid] += S->redd[tid+s]; __syncthreads(); }
        if (tid == 0) __stcg(&g_costp[bid], S->redd[0]);
    }
    gbar(++tgt);
    if (sub == 0 && warp == 0) {
        double cv = __ldcg(&g_costp[nb * 32 + lane]);
#pragma unroll
        for (int o = 16; o; o >>= 1)
            cv += __shfl_xor_sync(0xffffffffu, cv, o);
        if (lane == 0)
            gout[nb] = (float)(-(double)EPSV * (double)LN2F * cv);
    }
}

extern "C" void kernel_launch(void* const* d_in, const int* in_sizes, int n_in,
                              void* d_out, int out_size) {
    const float* x  = (const float*)d_in[0];
    const float* y  = (const float*)d_in[1];
    const float* xw = (const float*)d_in[2];
    const float* yw = (const float*)d_in[3];
    float* out = (float*)d_out;
    size_t smem = sizeof(Smem);
    cudaFuncSetAttribute(sinkhorn_kernel, cudaFuncAttributeMaxDynamicSharedMemorySize, (int)smem);
    sinkhorn_kernel<<<NCTA, TPB, smem>>>(x, y, xw, yw, out);
}